// round 15
// baseline (speedup 1.0000x reference)
#include <cuda_runtime.h>

#define BT 320
#define NWARP 10
#define PTS 640                      // points per CTA (2 per thread)
#define RHO_F 1060.0f
#define CCFL_F 0.9f
#define EPS_AF 1e-6f
#define MAX_CTA 160
#define MAX_T 256

// Critical-role warps (hi-wid-first arbiter).
#define SPIN_TID  ((NWARP - 1) * 32)   // 288: sync spinner
#define EDGEL_TID ((NWARP - 2) * 32)   // 256: left-edge poller
#define EDGER_TID ((NWARP - 3) * 32)   // 224: right-edge poller

// Persistent scratch. g_sync[t] = {smax_bits (red.max), count (red.add)}.
__device__ uint2  g_sync[MAX_T];
__device__ float4 g_edgeL[2][MAX_CTA];   // [buf][cta] first-point {A,Q,FQ,tag}
__device__ float4 g_edgeR[2][MAX_CTA];   // [buf][cta] last-point  {A,Q,FQ,tag}

__device__ __forceinline__ uint2 ld_acq_v2(const uint2* p) {
    uint2 v;
    asm volatile("ld.acquire.gpu.global.v2.u32 {%0,%1}, [%2];"
                 : "=r"(v.x), "=r"(v.y) : "l"(p) : "memory");
    return v;
}
__device__ __forceinline__ float4 ld_acq_v4(const float4* p) {
    float4 v;
    asm volatile("ld.acquire.gpu.global.v4.f32 {%0,%1,%2,%3}, [%4];"
                 : "=f"(v.x), "=f"(v.y), "=f"(v.z), "=f"(v.w) : "l"(p) : "memory");
    return v;
}
__device__ __forceinline__ void st_weak_v4(float4* p, float4 v) {
    asm volatile("st.global.v4.f32 [%0], {%1,%2,%3,%4};"
                 :: "l"(p), "f"(v.x), "f"(v.y), "f"(v.z), "f"(v.w) : "memory");
}
__device__ __forceinline__ void red_max_relaxed(unsigned* p, unsigned v) {
    asm volatile("red.relaxed.gpu.global.max.u32 [%0], %1;" :: "l"(p), "r"(v) : "memory");
}
__device__ __forceinline__ void red_add_release(unsigned* p, unsigned v) {
    asm volatile("red.release.gpu.global.add.u32 [%0], %1;" :: "l"(p), "r"(v) : "memory");
}
__device__ __forceinline__ float sqrt_fast(float x) {
    float y; asm("sqrt.approx.f32 %0, %1;" : "=f"(y) : "f"(x)); return y;
}
__device__ __forceinline__ float rsqrt_fast(float x) {
    float y; asm("rsqrt.approx.f32 %0, %1;" : "=f"(y) : "f"(x)); return y;
}

__global__ void sim_init_kernel() {
    int i = blockIdx.x * blockDim.x + threadIdx.x;
    if (i < MAX_T) g_sync[i] = make_uint2(0u, 0u);
    if (i < 2 * MAX_CTA) {
        float tg = __int_as_float(-1);
        ((float4*)g_edgeL)[i].w = tg;
        ((float4*)g_edgeR)[i].w = tg;
    }
}

__global__ void __launch_bounds__(BT, 1) sim_kernel(
    const float* __restrict__ Rs,
    const float* __restrict__ sim_dat,      // (2, M)
    const float* __restrict__ sdc,          // (11, M)
    const float* __restrict__ input_data,   // (T,)
    const int*   __restrict__ strides,      // (3, 2)
    float*       __restrict__ out,          // (T, 3)
    int M, int T)
{
    __shared__ float4 sE0[2][BT];     // point0 state per thread {A,Q,FQ,_}
    __shared__ float4 sE1[2][BT];     // point1 state per thread
    __shared__ int    wmax[NWARP];
    __shared__ float  bc[9];          // [0]=lam  [3..5]=left AQF  [6..8]=right AQF
    __shared__ float  sIn[256];

    const int tid  = threadIdx.x;
    const int lane = tid & 31;
    const int wid  = tid >> 5;
    const int cta  = blockIdx.x;
    const int nCTA = gridDim.x;
    const int g0   = cta * PTS + 2 * tid;       // this thread's two points: g0, g0+1

    for (int i = tid; i < T; i += BT) sIn[i] = input_data[i];
    if (tid >= 3 && tid < 9) bc[tid] = 1.0f;

    // softplus(Rs) once
    float rsv[4];
#pragma unroll
    for (int j = 0; j < 4; j++) {
        float x = Rs[j];
        rsv[j] = fmaxf(x, 0.0f) + log1pf(expf(-fabsf(x)));
    }

    const int st0 = strides[0], st1 = strides[2], st2 = strides[4];
    const int en0 = strides[1] - 1, en1 = strides[3] - 1, en2 = strides[5] - 1;
    const int mid0 = (strides[0] + strides[1]) >> 1;
    const int mid1 = (strides[2] + strides[3]) >> 1;
    const int mid2 = (strides[4] + strides[5]) >> 1;

    // per-point state/constants (p = 0,1)
    float A_[2], Q_[2], FQ_[2], sq_[2];
    float rA0_[2], beta_[2], cc_[2], fqc_[2], Rtot_[2];
    bool  act_[2], isS_[2], isE_[2], intr_[2];
    int   midv_[2];

#pragma unroll
    for (int p = 0; p < 2; p++) {
        int g = g0 + p;
        bool act = g < M;
        act_[p] = act;
        isS_[p] = act && (g == st0 || g == st1 || g == st2);
        isE_[p] = act && (g == en0 || g == en1 || g == en2);
        intr_[p] = act && g > 0 && g < M - 1;
        midv_[p] = (g == mid0) ? 0 : (g == mid1) ? 1 : (g == mid2) ? 2 : -1;
        A_[p] = 1.0f; Q_[p] = 0.0f; rA0_[p] = 1.0f; beta_[p] = 1.0f; Rtot_[p] = 1.0f;
        float iA0 = 1.0f;
        if (act) {
            A_[p] = fmaxf(sim_dat[g], EPS_AF);
            Q_[p] = 0.1f * sim_dat[M + g];
            iA0 = __fdividef(1.0f, sdc[g] + 0.5f);
            beta_[p] = sdc[M + g] + 1.0f;
            if (isE_[p]) {
                float R1 = sdc[7 * M + g] + 0.5f;
                float R2 = sdc[8 * M + g] + 0.5f;
                bool m1 = (g >= strides[2]) && (g < strides[3]);
                bool m2 = (g >= strides[4]) && (g < strides[5]);
                if (m1)      { R1 *= rsv[0]; R2 *= rsv[1]; }
                else if (m2) { R1 *= rsv[2]; R2 *= rsv[3]; }
                Rtot_[p] = R1 + R2;
            }
        }
        rA0_[p] = sqrt_fast(iA0);
        cc_[p]  = beta_[p] * (0.5f / RHO_F);
        fqc_[p] = beta_[p] * iA0 * (1.0f / (3.0f * RHO_F));
    }

    // ---- prologue: derived state, publish ----
    float sval = 0.0f;
#pragma unroll
    for (int p = 0; p < 2; p++) {
        sq_[p] = 1.0f; FQ_[p] = 0.0f;
        if (act_[p]) {
            float s1 = rsqrt_fast(A_[p]);
            float sqrtA = A_[p] * s1;
            sq_[p] = sqrtA * rA0_[p];
            float u = (Q_[p] * s1) * s1;
            float c = sqrt_fast(cc_[p] * sq_[p]);
            sval = fmaxf(sval, fabsf(u) + c);
            FQ_[p] = fmaf(Q_[p], u, fqc_[p] * A_[p] * sq_[p]);
        }
    }
    sE0[0][tid] = make_float4(A_[0], Q_[0], FQ_[0], 0.f);
    sE1[0][tid] = make_float4(A_[1], Q_[1], FQ_[1], 0.f);
    if (tid == 0)      st_weak_v4(&g_edgeL[0][cta], make_float4(A_[0], Q_[0], FQ_[0], __int_as_float(0)));
    if (tid == BT - 1) st_weak_v4(&g_edgeR[0][cta], make_float4(A_[1], Q_[1], FQ_[1], __int_as_float(0)));
    {
        int wv = __reduce_max_sync(0xFFFFFFFFu, __float_as_int(sval));
        if (lane == 0) wmax[wid] = wv;
    }
    __syncthreads();
    if (wid == NWARP - 1) {
        int v = __reduce_max_sync(0xFFFFFFFFu, (lane < NWARP) ? wmax[lane] : 0);
        if (lane == 0) {
            red_max_relaxed(&g_sync[0].x, (unsigned)v);
            red_add_release(&g_sync[0].y, 1u);
        }
    }

    const bool haveL = tid > 0, haveR = tid < BT - 1;
    const bool pollL = (cta > 0), pollR = (cta + 1 < nCTA);

    for (int t = 0; t < T; ++t) {
        const int b = t & 1, nb = b ^ 1;

        // ---- PRE-BARRIER stencil (lam*0.5*smax = 0.45 is constant) ----
        float4 Lh, Rh;
        float dA1[2], dQ1[2], cA[2], cQ[2];
        if (haveL && haveR) {
            Lh = sE1[b][tid - 1];       // left neighbor = prev thread's point1
            Rh = sE0[b][tid + 1];       // right neighbor = next thread's point0
            // point0: L=Lh, R=point1(regs)
            dA1[0] = 0.5f * (Q_[1] - Lh.y);
            dQ1[0] = 0.5f * (FQ_[1] - Lh.z);
            cA[0]  = fmaf(0.45f, A_[1] - 2.0f * A_[0] + Lh.x, A_[0]);
            cQ[0]  = fmaf(0.45f, Q_[1] - 2.0f * Q_[0] + Lh.y, Q_[0]);
            // point1: L=point0(regs), R=Rh
            dA1[1] = 0.5f * (Rh.y - Q_[0]);
            dQ1[1] = 0.5f * (Rh.z - FQ_[0]);
            cA[1]  = fmaf(0.45f, Rh.x - 2.0f * A_[1] + A_[0], A_[1]);
            cQ[1]  = fmaf(0.45f, Rh.y - 2.0f * Q_[1] + Q_[0], Q_[1]);
        }
        float P0 = beta_[0] * (sq_[0] - 1.0f);
        float P1 = beta_[1] * (sq_[1] - 1.0f);
        if (midv_[0] >= 0) out[t * 3 + midv_[0]] = P0;
        if (midv_[1] >= 0) out[t * 3 + midv_[1]] = P1;
        const float Qe0 = isE_[0] ? __fdividef(P0, Rtot_[0]) : 0.0f;
        const float Qe1 = isE_[1] ? __fdividef(P1, Rtot_[1]) : 0.0f;

        // ---- barrier + prefetch: scalar spins in the highest warps ----
        if (tid == SPIN_TID) {
            uint2 s;
            do { s = ld_acq_v2(&g_sync[t]); } while (s.y != (unsigned)nCTA);
            bc[0] = __fdividef(CCFL_F, __uint_as_float(s.x));
        } else if (tid == EDGEL_TID && pollL) {
            float4 e;
            do { e = ld_acq_v4(&g_edgeR[b][cta - 1]); } while (__float_as_int(e.w) != t);
            bc[3] = e.x; bc[4] = e.y; bc[5] = e.z;
        } else if (tid == EDGER_TID && pollR) {
            float4 e;
            do { e = ld_acq_v4(&g_edgeL[b][cta + 1]); } while (__float_as_int(e.w) != t);
            bc[6] = e.x; bc[7] = e.y; bc[8] = e.z;
        }
        __syncthreads();
        const float lam = bc[0];

        // boundary threads build their stencils now (halo staged in bc)
        if (!haveL || !haveR) {
            if (!haveL) { Lh.x = bc[3]; Lh.y = bc[4]; Lh.z = bc[5]; }
            else        { Lh = sE1[b][tid - 1]; }
            if (!haveR) { Rh.x = bc[6]; Rh.y = bc[7]; Rh.z = bc[8]; }
            else        { Rh = sE0[b][tid + 1]; }
            dA1[0] = 0.5f * (Q_[1] - Lh.y);
            dQ1[0] = 0.5f * (FQ_[1] - Lh.z);
            cA[0]  = fmaf(0.45f, A_[1] - 2.0f * A_[0] + Lh.x, A_[0]);
            cQ[0]  = fmaf(0.45f, Q_[1] - 2.0f * Q_[0] + Lh.y, Q_[0]);
            dA1[1] = 0.5f * (Rh.y - Q_[0]);
            dQ1[1] = 0.5f * (Rh.z - FQ_[0]);
            cA[1]  = fmaf(0.45f, Rh.x - 2.0f * A_[1] + A_[0], A_[1]);
            cQ[1]  = fmaf(0.45f, Rh.y - 2.0f * Q_[1] + Q_[0], Q_[1]);
        }

        // ---- POST-BARRIER: update + derived chain (two independent chains = ILP) ----
        float An0 = intr_[0] ? cA[0] - lam * dA1[0] : A_[0];
        float Qn0 = intr_[0] ? cQ[0] - lam * dQ1[0] : Q_[0];
        float An1 = intr_[1] ? cA[1] - lam * dA1[1] : A_[1];
        float Qn1 = intr_[1] ? cQ[1] - lam * dQ1[1] : Q_[1];
        if (isS_[0]) Qn0 = sIn[t];
        if (isS_[1]) Qn1 = sIn[t];
        if (isE_[0]) Qn0 = Qe0;
        if (isE_[1]) Qn1 = Qe1;
        An0 = fmaxf(An0, EPS_AF);
        An1 = fmaxf(An1, EPS_AF);

        float sval0 = 0.0f, sval1 = 0.0f;
        if (act_[0]) {
            A_[0] = An0; Q_[0] = Qn0;
            float s1 = rsqrt_fast(A_[0]);
            float sqrtA = A_[0] * s1;
            sq_[0] = sqrtA * rA0_[0];
            float u = (Q_[0] * s1) * s1;
            float c = sqrt_fast(cc_[0] * sq_[0]);
            sval0 = fabsf(u) + c;
            FQ_[0] = fmaf(Q_[0], u, fqc_[0] * A_[0] * sq_[0]);
        }
        if (act_[1]) {
            A_[1] = An1; Q_[1] = Qn1;
            float s1 = rsqrt_fast(A_[1]);
            float sqrtA = A_[1] * s1;
            sq_[1] = sqrtA * rA0_[1];
            float u = (Q_[1] * s1) * s1;
            float c = sqrt_fast(cc_[1] * sq_[1]);
            sval1 = fabsf(u) + c;
            FQ_[1] = fmaf(Q_[1], u, fqc_[1] * A_[1] * sq_[1]);
        }

        // publish early (in-word tags; weak stores)
        sE0[nb][tid] = make_float4(A_[0], Q_[0], FQ_[0], 0.f);
        sE1[nb][tid] = make_float4(A_[1], Q_[1], FQ_[1], 0.f);
        if (tid == 0)      st_weak_v4(&g_edgeL[nb][cta], make_float4(A_[0], Q_[0], FQ_[0], __int_as_float(t + 1)));
        if (tid == BT - 1) st_weak_v4(&g_edgeR[nb][cta], make_float4(A_[1], Q_[1], FQ_[1], __int_as_float(t + 1)));
        int wv = __reduce_max_sync(0xFFFFFFFFu, __float_as_int(fmaxf(sval0, sval1)));
        if (lane == 0) wmax[wid] = wv;
        __syncthreads();
        if (wid == NWARP - 1) {
            int v = __reduce_max_sync(0xFFFFFFFFu, (lane < NWARP) ? wmax[lane] : 0);
            if (lane == 0) {
                red_max_relaxed(&g_sync[t + 1].x, (unsigned)v);
                red_add_release(&g_sync[t + 1].y, 1u);
            }
        }
    }
}

extern "C" void kernel_launch(void* const* d_in, const int* in_sizes, int n_in,
                              void* d_out, int out_size) {
    const float* Rs         = (const float*)d_in[0];
    const float* sim_dat    = (const float*)d_in[1];
    const float* sdc        = (const float*)d_in[2];
    const float* input_data = (const float*)d_in[3];
    const int*   strides    = (const int*)d_in[4];

    int M = in_sizes[1] / 2;     // sim_dat is (2, M)
    int T = in_sizes[3];         // input_data length

    int nCTA = (M + PTS - 1) / PTS;   // 141 — 1 CTA/SM, all co-resident

    sim_init_kernel<<<2, 256>>>();
    sim_kernel<<<nCTA, BT>>>(Rs, sim_dat, sdc, input_data, strides, (float*)d_out, M, T);
}

// round 16
// speedup vs baseline: 1.0859x; 1.0859x over previous
#include <cuda_runtime.h>

#define BT 640
#define NWARP 20
#define RHO_F 1060.0f
#define CCFL_F 0.9f
#define EPS_AF 1e-6f
#define MAX_CTA 160
#define MAX_T 256

// Critical-role warps (hi-wid-first arbiter).
#define SPIN_TID  ((NWARP - 1) * 32)   // 608: sync spinner
#define EDGEL_TID ((NWARP - 2) * 32)   // 576: left-edge poller
#define EDGER_TID ((NWARP - 3) * 32)   // 544: right-edge poller

// Persistent scratch. g_sync[t] = {smax_bits (red.max), count (red.add)}.
__device__ uint2  g_sync[MAX_T];
__device__ float4 g_edgeL[2][MAX_CTA];   // [buf][cta] first-point {A,Q,FQ,tag}
__device__ float4 g_edgeR[2][MAX_CTA];   // [buf][cta] last-point  {A,Q,FQ,tag}

// Relaxed gpu-scope loads: coherent at L2 (bypass stale L1), no acquire fence.
// Safe here: lam rides in the polled 8B word; edges are tag-in-word 16B atoms.
__device__ __forceinline__ uint2 ld_rlx_v2(const uint2* p) {
    uint2 v;
    asm volatile("ld.relaxed.gpu.global.v2.u32 {%0,%1}, [%2];"
                 : "=r"(v.x), "=r"(v.y) : "l"(p) : "memory");
    return v;
}
__device__ __forceinline__ float4 ld_rlx_v4(const float4* p) {
    float4 v;
    asm volatile("ld.relaxed.gpu.global.v4.f32 {%0,%1,%2,%3}, [%4];"
                 : "=f"(v.x), "=f"(v.y), "=f"(v.z), "=f"(v.w) : "l"(p) : "memory");
    return v;
}
__device__ __forceinline__ void st_weak_v4(float4* p, float4 v) {
    asm volatile("st.global.v4.f32 [%0], {%1,%2,%3,%4};"
                 :: "l"(p), "f"(v.x), "f"(v.y), "f"(v.z), "f"(v.w) : "memory");
}
__device__ __forceinline__ void red_max_relaxed(unsigned* p, unsigned v) {
    asm volatile("red.relaxed.gpu.global.max.u32 [%0], %1;" :: "l"(p), "r"(v) : "memory");
}
__device__ __forceinline__ void red_add_release(unsigned* p, unsigned v) {
    asm volatile("red.release.gpu.global.add.u32 [%0], %1;" :: "l"(p), "r"(v) : "memory");
}
__device__ __forceinline__ float sqrt_fast(float x) {
    float y; asm("sqrt.approx.f32 %0, %1;" : "=f"(y) : "f"(x)); return y;
}

__global__ void sim_init_kernel() {
    int i = blockIdx.x * blockDim.x + threadIdx.x;
    if (i < MAX_T) g_sync[i] = make_uint2(0u, 0u);
    if (i < 2 * MAX_CTA) {   // reset edge tags (replay safety)
        float tg = __int_as_float(-1);
        ((float4*)g_edgeL)[i].w = tg;
        ((float4*)g_edgeR)[i].w = tg;
    }
}

__global__ void __launch_bounds__(BT, 1) sim_kernel(
    const float* __restrict__ Rs,
    const float* __restrict__ sim_dat,      // (2, M)
    const float* __restrict__ sdc,          // (11, M)
    const float* __restrict__ input_data,   // (T,)
    const int*   __restrict__ strides,      // (3, 2)
    float*       __restrict__ out,          // (T, 3)
    int M, int T)
{
    __shared__ float4 sAQF[2][BT];    // packed state {A, Q, FQ, _}
    __shared__ int    wmax[NWARP];
    __shared__ float  bc[9];          // [0]=lam  [3..5]=left AQF  [6..8]=right AQF
    __shared__ float  sIn[256];

    const int tid  = threadIdx.x;
    const int lane = tid & 31;
    const int wid  = tid >> 5;
    const int cta  = blockIdx.x;
    const int nCTA = gridDim.x;
    const int gi   = cta * BT + tid;
    const bool active = gi < M;

    for (int i = tid; i < T; i += BT) sIn[i] = input_data[i];
    if (tid >= 3 && tid < 9) bc[tid] = 1.0f;

    const int st0 = strides[0], st1 = strides[2], st2 = strides[4];
    const int en0 = strides[1] - 1, en1 = strides[3] - 1, en2 = strides[5] - 1;
    const int mid0 = (strides[0] + strides[1]) >> 1;
    const int mid1 = (strides[2] + strides[3]) >> 1;
    const int mid2 = (strides[4] + strides[5]) >> 1;

    const bool is_start = active && (gi == st0 || gi == st1 || gi == st2);
    const bool is_end   = active && (gi == en0 || gi == en1 || gi == en2);
    const bool interior = active && gi > 0 && gi < M - 1;
    const int  midv = (gi == mid0) ? 0 : (gi == mid1) ? 1 : (gi == mid2) ? 2 : -1;

    float A = 1.0f, Q = 0.0f, invA0 = 1.0f, beta = 1.0f, Rtot = 1.0f;
    if (active) {
        A = fmaxf(sim_dat[gi], EPS_AF);
        Q = 0.1f * sim_dat[M + gi];
        invA0 = __fdividef(1.0f, sdc[gi] + 0.5f);
        beta = sdc[M + gi] + 1.0f;
        if (is_end) {
            float R1 = sdc[7 * M + gi] + 0.5f;
            float R2 = sdc[8 * M + gi] + 0.5f;
            bool m1 = (gi >= strides[2]) && (gi < strides[3]);
            bool m2 = (gi >= strides[4]) && (gi < strides[5]);
            float rsv[4];
#pragma unroll
            for (int j = 0; j < 4; j++) {
                float x = Rs[j];
                rsv[j] = fmaxf(x, 0.0f) + log1pf(expf(-fabsf(x)));   // softplus
            }
            if (m1)      { R1 *= rsv[0]; R2 *= rsv[1]; }
            else if (m2) { R1 *= rsv[2]; R2 *= rsv[3]; }
            Rtot = R1 + R2;
        }
    }
    const float cc  = beta * (0.5f / RHO_F);
    const float fqc = beta * invA0 * (1.0f / (3.0f * RHO_F));

    // ---- prologue: state-0 derived quantities, publish ----
    float sq = 1.0f, FQ = 0.0f, sval = 0.0f;
    if (active) {
        sq = sqrt_fast(A * invA0);
        float u = __fdividef(Q, A);
        float c = sqrt_fast(cc * sq);
        sval = fabsf(u) + c;
        FQ = Q * u + fqc * A * sq;
    }
    sAQF[0][tid] = make_float4(A, Q, FQ, 0.f);
    if (tid == 0)      st_weak_v4(&g_edgeL[0][cta], make_float4(A, Q, FQ, __int_as_float(0)));
    if (tid == BT - 1) st_weak_v4(&g_edgeR[0][cta], make_float4(A, Q, FQ, __int_as_float(0)));
    {
        int wv = __reduce_max_sync(0xFFFFFFFFu, __float_as_int(sval));
        if (lane == 0) wmax[wid] = wv;
    }
    __syncthreads();
    if (wid == NWARP - 1) {
        int v = __reduce_max_sync(0xFFFFFFFFu, (lane < NWARP) ? wmax[lane] : 0);
        if (lane == 0) {
            red_max_relaxed(&g_sync[0].x, (unsigned)v);
            red_add_release(&g_sync[0].y, 1u);
        }
    }

    const bool haveL = tid > 0, haveR = tid < BT - 1;
    const bool pollL = (cta > 0), pollR = (cta + 1 < nCTA);

    for (int t = 0; t < T; ++t) {
        const int b = t & 1, nb = b ^ 1;

        // ---- PRE-BARRIER: stencil terms not needing lam ----
        // lam*0.5*smax = 0.45 (constant):
        //   A_new = [A + 0.45*(Ar-2A+Al)] - lam*0.5*(Qr-Ql)
        //   Q_new = [Q + 0.45*(Qr-2Q+Ql)] - lam*0.5*(Fr-Fl)
        float4 Lh, Rh;
        float dA1 = 0.f, dQ1 = 0.f, cA = A, cQ = Q;
        if (haveL && haveR) {
            Lh = sAQF[b][tid - 1]; Rh = sAQF[b][tid + 1];
            dA1 = 0.5f * (Rh.y - Lh.y);
            dQ1 = 0.5f * (Rh.z - Lh.z);
            cA  = fmaf(0.45f, Rh.x - 2.0f * A + Lh.x, A);
            cQ  = fmaf(0.45f, Rh.y - 2.0f * Q + Lh.y, Q);
        }
        const float P = beta * (sq - 1.0f);
        if (midv >= 0) out[t * 3 + midv] = P;
        const float Qend = is_end ? __fdividef(P, Rtot) : 0.0f;

        // ---- barrier + prefetch ----
        if (tid == SPIN_TID) {
            // sync spinner: depth-1 dependent spin (self-throttled; R9/R12 proved
            // extra probe pressure on the RMW-hot line backfires), relaxed load.
            uint2 s;
            do { s = ld_rlx_v2(&g_sync[t]); } while (s.y != (unsigned)nCTA);
            bc[0] = __fdividef(CCFL_F, __uint_as_float(s.x));   // lam
        } else if (tid == EDGEL_TID && pollL) {
            // edge lines: single reader + single writer — depth-2 pipelined poll
            // is congestion-free and halves the detect quantization tail.
            const float4* p = &g_edgeR[b][cta - 1];
            float4 e0 = ld_rlx_v4(p);
            float4 e1 = ld_rlx_v4(p);
            while (__float_as_int(e0.w) != t) { e0 = e1; e1 = ld_rlx_v4(p); }
            bc[3] = e0.x; bc[4] = e0.y; bc[5] = e0.z;
        } else if (tid == EDGER_TID && pollR) {
            const float4* p = &g_edgeL[b][cta + 1];
            float4 e0 = ld_rlx_v4(p);
            float4 e1 = ld_rlx_v4(p);
            while (__float_as_int(e0.w) != t) { e0 = e1; e1 = ld_rlx_v4(p); }
            bc[6] = e0.x; bc[7] = e0.y; bc[8] = e0.z;
        }
        __syncthreads();
        const float lam = bc[0];

        // edge threads: halo staged in bc — zero L2 on the post-barrier path
        if (!haveL || !haveR) {
            if (!haveL) { Lh.x = bc[3]; Lh.y = bc[4]; Lh.z = bc[5]; }
            else        { Lh = sAQF[b][tid - 1]; }
            if (!haveR) { Rh.x = bc[6]; Rh.y = bc[7]; Rh.z = bc[8]; }
            else        { Rh = sAQF[b][tid + 1]; }
            dA1 = 0.5f * (Rh.y - Lh.y);
            dQ1 = 0.5f * (Rh.z - Lh.z);
            cA  = fmaf(0.45f, Rh.x - 2.0f * A + Lh.x, A);
            cQ  = fmaf(0.45f, Rh.y - 2.0f * Q + Lh.y, Q);
        }

        // ---- POST-BARRIER: short chain ----
        float An = interior ? cA - lam * dA1 : A;
        float Qn = interior ? cQ - lam * dQ1 : Q;
        if (is_start) Qn = sIn[t];
        if (is_end)   Qn = Qend;
        An = fmaxf(An, EPS_AF);

        float snew = 0.0f;
        if (active) {
            A = An; Q = Qn;
            sq = sqrt_fast(A * invA0);
            float u = __fdividef(Q, A);
            float c = sqrt_fast(cc * sq);
            snew = fabsf(u) + c;
            FQ = fmaf(Q, u, fqc * A * sq);
        }

        // publish early (in-word tags; weak stores — consumers value-gate)
        sAQF[nb][tid] = make_float4(A, Q, FQ, 0.f);
        if (tid == 0)      st_weak_v4(&g_edgeL[nb][cta], make_float4(A, Q, FQ, __int_as_float(t + 1)));
        if (tid == BT - 1) st_weak_v4(&g_edgeR[nb][cta], make_float4(A, Q, FQ, __int_as_float(t + 1)));
        int wv = __reduce_max_sync(0xFFFFFFFFu, __float_as_int(snew));
        if (lane == 0) wmax[wid] = wv;
        __syncthreads();
        if (wid == NWARP - 1) {
            int v = __reduce_max_sync(0xFFFFFFFFu, (lane < NWARP) ? wmax[lane] : 0);
            if (lane == 0) {
                red_max_relaxed(&g_sync[t + 1].x, (unsigned)v);
                red_add_release(&g_sync[t + 1].y, 1u);   // release: max applied before count at LTS
            }
        }
    }
}

extern "C" void kernel_launch(void* const* d_in, const int* in_sizes, int n_in,
                              void* d_out, int out_size) {
    const float* Rs         = (const float*)d_in[0];
    const float* sim_dat    = (const float*)d_in[1];
    const float* sdc        = (const float*)d_in[2];
    const float* input_data = (const float*)d_in[3];
    const int*   strides    = (const int*)d_in[4];

    int M = in_sizes[1] / 2;     // sim_dat is (2, M)
    int T = in_sizes[3];         // input_data length

    int nCTA = (M + BT - 1) / BT;   // 141 — 1 CTA/SM, all co-resident

    sim_init_kernel<<<2, 256>>>();
    sim_kernel<<<nCTA, BT>>>(Rs, sim_dat, sdc, input_data, strides, (float*)d_out, M, T);
}